// round 1
// baseline (speedup 1.0000x reference)
#include <cuda_runtime.h>

#define N_NODES  150000
#define N_EDGES  2400000
#define DIM      64
#define NEG_SLOPE 0.01f

// Scratch (allocation-free): ego and side message accumulator, 38.4 MB each.
__device__ float g_ego[N_NODES * DIM];
__device__ float g_side[N_NODES * DIM];

// ---------------------------------------------------------------------------
// init: copy ego input -> g_ego, write output cols [0,64), zero g_side.
// One thread per float4. Grid: N_NODES*16/256 = 9375 blocks.
// ---------------------------------------------------------------------------
__global__ void init_kernel(const float* __restrict__ ego_in,
                            float* __restrict__ out) {
    int t = blockIdx.x * 256 + threadIdx.x;        // float4 index, < N_NODES*16
    float4 v = ((const float4*)ego_in)[t];
    ((float4*)g_ego)[t]  = v;
    ((float4*)g_side)[t] = make_float4(0.f, 0.f, 0.f, 0.f);
    int i = t >> 4;        // node
    int c = t & 15;        // float4 chunk within row
    // out row = 256 floats = 64 float4; layer-0 block is chunks [0,16)
    ((float4*)out)[i * 64 + c] = v;
}

// ---------------------------------------------------------------------------
// spmm: side[row] += val * ego[col].  16 threads per edge, float4 per thread,
// vectorized no-return reduction (red.global.add.v4.f32).
// Grid: N_EDGES*16/256 = 150000 blocks.
// ---------------------------------------------------------------------------
__global__ void spmm_kernel(const int*   __restrict__ rows,
                            const int*   __restrict__ cols,
                            const float* __restrict__ vals) {
    int t = blockIdx.x * 256 + threadIdx.x;        // < N_EDGES*16
    int e = t >> 4;
    int c = t & 15;
    int r  = rows[e];
    int cl = cols[e];
    float v = vals[e];
    const float4* egop = (const float4*)g_ego;
    float4 x = __ldg(egop + (cl * 16 + c));
    float4 m = make_float4(v * x.x, v * x.y, v * x.z, v * x.w);
    float* dst = g_side + r * DIM + c * 4;
    asm volatile("red.global.add.v4.f32 [%0], {%1,%2,%3,%4};"
                 :: "l"(dst), "f"(m.x), "f"(m.y), "f"(m.z), "f"(m.w)
                 : "memory");
}

// ---------------------------------------------------------------------------
// update (fused): for each node i
//   add  = ego + side ; prod = ego * side
//   sum  = lrelu(add  @ W1^T + b1)
//   bi   = lrelu(prod @ W2^T + b2)
//   ego' = sum + bi        (written back to g_ego, in place)
//   out[:, col_off:col_off+64] = ego' / max(||ego'||, 1e-12)
//   g_side = 0             (ready for next layer's spmm)
//
// Block: 256 threads, 16 nodes per block (exact: 150000 = 9375 * 16).
// Thread (slot = tid>>6, j = tid&63) computes output dim j for 4 nodes,
// so W1/W2 shared reads are amortized 4x; float4 everywhere.
// ---------------------------------------------------------------------------
__global__ void update_kernel(const float* __restrict__ W1,
                              const float* __restrict__ b1,
                              const float* __restrict__ W2,
                              const float* __restrict__ b2,
                              float* __restrict__ out,
                              int col_off) {
    __shared__ float sW1[64 * 68];    // row-major, row stride 68 (pad 4) -> conflict-free LDS.128
    __shared__ float sW2[64 * 68];
    __shared__ float sb1[64], sb2[64];
    __shared__ float sA[16 * 64];     // add  vectors for 16 nodes
    __shared__ float sP[16 * 64];     // prod vectors for 16 nodes
    __shared__ float sRed[8][4];      // per-warp partial sum-of-squares

    int tid = threadIdx.x;

    // Stage W (row-major with pad). Coalesced global reads; shared writes
    // hit distinct banks ((4j + d) % 32 over consecutive d).
    for (int idx = tid; idx < 4096; idx += 256) {
        int j = idx >> 6, d = idx & 63;
        sW1[j * 68 + d] = W1[idx];
        sW2[j * 68 + d] = W2[idx];
    }
    if (tid < 64) { sb1[tid] = b1[tid]; sb2[tid] = b2[tid]; }

    // Stage add/prod for this block's 16 nodes; zero side behind us.
    int gbase = blockIdx.x * (16 * DIM);
    for (int idx = tid; idx < 1024; idx += 256) {
        float e = g_ego[gbase + idx];
        float s = g_side[gbase + idx];
        sA[idx] = e + s;
        sP[idx] = e * s;
        g_side[gbase + idx] = 0.f;
    }
    __syncthreads();

    int j    = tid & 63;
    int slot = tid >> 6;              // 4 slots x 4 nodes each

    float y1[4], y2[4];
    #pragma unroll
    for (int n = 0; n < 4; n++) { y1[n] = sb1[j]; y2[n] = sb2[j]; }

    const float4* w1r = (const float4*)(sW1 + j * 68);
    const float4* w2r = (const float4*)(sW2 + j * 68);
    const float4* a4  = (const float4*)sA;
    const float4* p4  = (const float4*)sP;

    #pragma unroll
    for (int d4 = 0; d4 < 16; d4++) {
        float4 w1 = w1r[d4];
        float4 w2 = w2r[d4];
        #pragma unroll
        for (int n = 0; n < 4; n++) {
            int node = slot * 4 + n;
            float4 a = a4[node * 16 + d4];   // broadcast within warp
            float4 p = p4[node * 16 + d4];
            y1[n] = fmaf(a.x, w1.x, fmaf(a.y, w1.y, fmaf(a.z, w1.z, fmaf(a.w, w1.w, y1[n]))));
            y2[n] = fmaf(p.x, w2.x, fmaf(p.y, w2.y, fmaf(p.z, w2.z, fmaf(p.w, w2.w, y2[n]))));
        }
    }

    float v[4], s2[4];
    #pragma unroll
    for (int n = 0; n < 4; n++) {
        float a = (y1[n] >= 0.f) ? y1[n] : NEG_SLOPE * y1[n];
        float b = (y2[n] >= 0.f) ? y2[n] : NEG_SLOPE * y2[n];
        v[n] = a + b;
        float ss = v[n] * v[n];
        #pragma unroll
        for (int off = 16; off; off >>= 1)
            ss += __shfl_xor_sync(0xffffffffu, ss, off);
        s2[n] = ss;
    }

    int warp = tid >> 5, lane = tid & 31;
    if (lane == 0) {
        #pragma unroll
        for (int n = 0; n < 4; n++) sRed[warp][n] = s2[n];
    }
    __syncthreads();

    #pragma unroll
    for (int n = 0; n < 4; n++) {
        float tot = sRed[slot * 2][n] + sRed[slot * 2 + 1][n];
        float inv = 1.0f / fmaxf(sqrtf(tot), 1e-12f);
        int i = blockIdx.x * 16 + slot * 4 + n;
        g_ego[i * DIM + j] = v[n];                  // unnormalized ego for next layer
        out[i * 256 + col_off + j] = v[n] * inv;    // normalized output block
    }
}

// ---------------------------------------------------------------------------
// Inputs (metadata order): edge_rows(i32), edge_cols(i32), edge_vals(f32),
// ego(f32 N*64), W1(3*64*64), b1(3*64), W2(3*64*64), b2(3*64).
// Output: float32 [150000, 256] = [ego | norm1 | norm2 | norm3] rows
// (ua rows 0..49999, ea rows 50000..149999 -> contiguous, identical layout).
// ---------------------------------------------------------------------------
extern "C" void kernel_launch(void* const* d_in, const int* in_sizes, int n_in,
                              void* d_out, int out_size) {
    const int*   rows = (const int*)  d_in[0];
    const int*   cols = (const int*)  d_in[1];
    const float* vals = (const float*)d_in[2];
    const float* ego  = (const float*)d_in[3];
    const float* W1   = (const float*)d_in[4];
    const float* b1   = (const float*)d_in[5];
    const float* W2   = (const float*)d_in[6];
    const float* b2   = (const float*)d_in[7];
    float* out = (float*)d_out;

    init_kernel<<<(N_NODES * 16) / 256, 256>>>(ego, out);            // 9375 blocks
    for (int k = 0; k < 3; k++) {
        spmm_kernel<<<(N_EDGES * 16) / 256, 256>>>(rows, cols, vals); // 150000 blocks
        update_kernel<<<N_NODES / 16, 256>>>(W1 + k * 4096, b1 + k * 64,
                                             W2 + k * 4096, b2 + k * 64,
                                             out, (k + 1) * 64);      // 9375 blocks
    }
}

// round 2
// speedup vs baseline: 1.8872x; 1.8872x over previous
#include <cuda_runtime.h>

#define N_NODES  150000
#define N_EDGES  2400000
#define DIM      64
#define NEG_SLOPE 0.01f
#define NODES_PER_BLK 24
#define UPD_BLOCKS (N_NODES / NODES_PER_BLK)   // 6250

// Scratch (allocation-free): ego and side message accumulator, 38.4 MB each.
__device__ float g_ego[N_NODES * DIM];
__device__ float g_side[N_NODES * DIM];

// ---------------------------------------------------------------------------
// dummy: occupies launch slot 0 so ncu's fixed "-s 5" lands on the second
// update kernel instead of the third spmm (diagnostic alignment, ~2us).
// ---------------------------------------------------------------------------
__global__ void dummy_kernel() {
    if (blockIdx.x == 0x40000000) g_side[0] = 0.f;   // never true
}

// ---------------------------------------------------------------------------
// init: copy ego input -> g_ego, write output cols [0,64), zero g_side.
// One thread per float4. Grid: N_NODES*16/256 = 9375 blocks.
// ---------------------------------------------------------------------------
__global__ void init_kernel(const float* __restrict__ ego_in,
                            float* __restrict__ out) {
    int t = blockIdx.x * 256 + threadIdx.x;        // float4 index, < N_NODES*16
    float4 v = ((const float4*)ego_in)[t];
    ((float4*)g_ego)[t]  = v;
    ((float4*)g_side)[t] = make_float4(0.f, 0.f, 0.f, 0.f);
    int i = t >> 4;        // node
    int c = t & 15;        // float4 chunk within row
    ((float4*)out)[i * 64 + c] = v;                // out row = 64 float4
}

// ---------------------------------------------------------------------------
// spmm: side[row] += val * ego[col].
// 4 edges per thread (same float4 chunk), so:
//   - indices/vals load as int4/float4 (1 LDG.128 per warp per array / 8 edges)
//   - 4 independent ego gathers in flight (MLP=4) before the 4 REDs
// t = group*16 + chunk; groups = E/4 = 600000; grid = 9.6M/256 = 37500 blocks.
// ---------------------------------------------------------------------------
__global__ void __launch_bounds__(256) spmm_kernel(
        const int*   __restrict__ rows,
        const int*   __restrict__ cols,
        const float* __restrict__ vals) {
    int t = blockIdx.x * 256 + threadIdx.x;
    int g = t >> 4;        // edge group of 4
    int c = t & 15;        // float4 chunk within the 64-float row
    int4   r4 = __ldg((const int4*)  rows + g);
    int4   c4 = __ldg((const int4*)  cols + g);
    float4 v4 = __ldg((const float4*)vals + g);
    const float4* egop = (const float4*)g_ego;
    float4 x0 = __ldg(egop + (c4.x * 16 + c));
    float4 x1 = __ldg(egop + (c4.y * 16 + c));
    float4 x2 = __ldg(egop + (c4.z * 16 + c));
    float4 x3 = __ldg(egop + (c4.w * 16 + c));

    float* d0 = g_side + r4.x * DIM + c * 4;
    float* d1 = g_side + r4.y * DIM + c * 4;
    float* d2 = g_side + r4.z * DIM + c * 4;
    float* d3 = g_side + r4.w * DIM + c * 4;
    asm volatile("red.global.add.v4.f32 [%0], {%1,%2,%3,%4};"
                 :: "l"(d0), "f"(v4.x*x0.x), "f"(v4.x*x0.y), "f"(v4.x*x0.z), "f"(v4.x*x0.w) : "memory");
    asm volatile("red.global.add.v4.f32 [%0], {%1,%2,%3,%4};"
                 :: "l"(d1), "f"(v4.y*x1.x), "f"(v4.y*x1.y), "f"(v4.y*x1.z), "f"(v4.y*x1.w) : "memory");
    asm volatile("red.global.add.v4.f32 [%0], {%1,%2,%3,%4};"
                 :: "l"(d2), "f"(v4.z*x2.x), "f"(v4.z*x2.y), "f"(v4.z*x2.z), "f"(v4.z*x2.w) : "memory");
    asm volatile("red.global.add.v4.f32 [%0], {%1,%2,%3,%4};"
                 :: "l"(d3), "f"(v4.w*x3.x), "f"(v4.w*x3.y), "f"(v4.w*x3.z), "f"(v4.w*x3.w) : "memory");
}

// ---------------------------------------------------------------------------
// update (fused): per node i
//   add = ego+side; prod = ego*side
//   ego' = lrelu(add@W1^T+b1) + lrelu(prod@W2^T+b2)
//   out[:, col_off:+64] = ego'/max(||ego'||,eps);  g_side = 0 (next layer)
// 24 nodes/block, 256 threads; thread (slot=tid>>6, j=tid&63) computes output
// dim j for 6 nodes -> each W float4 shared-load feeds 48 FMAs.
// Final layer (last=1) skips g_ego writeback + side zeroing (dead work;
// init redoes both each replay).
// ---------------------------------------------------------------------------
__global__ void __launch_bounds__(256) update_kernel(
        const float* __restrict__ W1, const float* __restrict__ b1,
        const float* __restrict__ W2, const float* __restrict__ b2,
        float* __restrict__ out, int col_off, int last) {
    __shared__ float sW1[64 * 68];    // row stride 68 (pad) -> conflict-free LDS.128
    __shared__ float sW2[64 * 68];
    __shared__ float sb1[64], sb2[64];
    __shared__ float sA[NODES_PER_BLK * 64];
    __shared__ float sP[NODES_PER_BLK * 64];
    __shared__ float sRed[8][6];

    int tid = threadIdx.x;

    // Stage W via float4 (1024 float4s each). sW1+j*68 is 16B-aligned (272B rows).
    for (int idx = tid; idx < 1024; idx += 256) {
        int j = idx >> 4, d4 = idx & 15;
        ((float4*)(sW1 + j * 68))[d4] = ((const float4*)W1)[idx];
        ((float4*)(sW2 + j * 68))[d4] = ((const float4*)W2)[idx];
    }
    if (tid < 64) { sb1[tid] = b1[tid]; sb2[tid] = b2[tid]; }

    // Stage add/prod for 24 nodes (384 float4); zero side behind us.
    int gbase4 = blockIdx.x * (NODES_PER_BLK * 16);   // float4 index
    for (int idx = tid; idx < NODES_PER_BLK * 16; idx += 256) {
        float4 e = ((const float4*)g_ego)[gbase4 + idx];
        float4 s = ((const float4*)g_side)[gbase4 + idx];
        ((float4*)sA)[idx] = make_float4(e.x + s.x, e.y + s.y, e.z + s.z, e.w + s.w);
        ((float4*)sP)[idx] = make_float4(e.x * s.x, e.y * s.y, e.z * s.z, e.w * s.w);
        if (!last) ((float4*)g_side)[gbase4 + idx] = make_float4(0.f, 0.f, 0.f, 0.f);
    }
    __syncthreads();

    int j    = tid & 63;
    int slot = tid >> 6;              // 4 slots x 6 nodes each

    float y1[6], y2[6];
    #pragma unroll
    for (int n = 0; n < 6; n++) { y1[n] = sb1[j]; y2[n] = sb2[j]; }

    const float4* w1r = (const float4*)(sW1 + j * 68);
    const float4* w2r = (const float4*)(sW2 + j * 68);
    const float4* a4  = (const float4*)sA;
    const float4* p4  = (const float4*)sP;

    #pragma unroll
    for (int d4 = 0; d4 < 16; d4++) {
        float4 w1 = w1r[d4];
        float4 w2 = w2r[d4];
        #pragma unroll
        for (int n = 0; n < 6; n++) {
            int node = slot * 6 + n;
            float4 a = a4[node * 16 + d4];   // broadcast within warp
            float4 p = p4[node * 16 + d4];
            y1[n] = fmaf(a.x, w1.x, fmaf(a.y, w1.y, fmaf(a.z, w1.z, fmaf(a.w, w1.w, y1[n]))));
            y2[n] = fmaf(p.x, w2.x, fmaf(p.y, w2.y, fmaf(p.z, w2.z, fmaf(p.w, w2.w, y2[n]))));
        }
    }

    float v[6];
    #pragma unroll
    for (int n = 0; n < 6; n++) {
        float a = (y1[n] >= 0.f) ? y1[n] : NEG_SLOPE * y1[n];
        float b = (y2[n] >= 0.f) ? y2[n] : NEG_SLOPE * y2[n];
        v[n] = a + b;
        float ss = v[n] * v[n];
        #pragma unroll
        for (int off = 16; off; off >>= 1)
            ss += __shfl_xor_sync(0xffffffffu, ss, off);
        if ((tid & 31) == 0) sRed[tid >> 5][n] = ss;
    }
    __syncthreads();

    #pragma unroll
    for (int n = 0; n < 6; n++) {
        float tot = sRed[slot * 2][n] + sRed[slot * 2 + 1][n];
        float inv = 1.0f / fmaxf(sqrtf(tot), 1e-12f);
        int i = blockIdx.x * NODES_PER_BLK + slot * 6 + n;
        if (!last) g_ego[i * DIM + j] = v[n];          // ego for next layer
        out[i * 256 + col_off + j] = v[n] * inv;       // normalized block
    }
}

// ---------------------------------------------------------------------------
// Inputs: edge_rows(i32), edge_cols(i32), edge_vals(f32), ego(f32 N*64),
// W1(3*64*64), b1(3*64), W2(3*64*64), b2(3*64).
// Output: float32 [150000, 256] rows = [ego | norm1 | norm2 | norm3].
// ---------------------------------------------------------------------------
extern "C" void kernel_launch(void* const* d_in, const int* in_sizes, int n_in,
                              void* d_out, int out_size) {
    const int*   rows = (const int*)  d_in[0];
    const int*   cols = (const int*)  d_in[1];
    const float* vals = (const float*)d_in[2];
    const float* ego  = (const float*)d_in[3];
    const float* W1   = (const float*)d_in[4];
    const float* b1   = (const float*)d_in[5];
    const float* W2   = (const float*)d_in[6];
    const float* b2   = (const float*)d_in[7];
    float* out = (float*)d_out;

    dummy_kernel<<<1, 32>>>();                                        // launch 0
    init_kernel<<<(N_NODES * 16) / 256, 256>>>(ego, out);             // launch 1
    for (int k = 0; k < 3; k++) {
        spmm_kernel<<<(N_EDGES / 4 * 16) / 256, 256>>>(rows, cols, vals);
        update_kernel<<<UPD_BLOCKS, 256>>>(W1 + k * 4096, b1 + k * 64,
                                           W2 + k * 4096, b2 + k * 64,
                                           out, (k + 1) * 64, k == 2);
    }
}

// round 5
// speedup vs baseline: 2.0785x; 1.1014x over previous
#include <cuda_runtime.h>

#define N_NODES  150000
#define N_PAD    150016          // 2344 * 64
#define N_EDGES  2400000
#define DIM      64
#define NEG_SLOPE 0.01f
#define UPD_BLOCKS 2344          // 64 nodes per block

// Dynamic smem layout for update_kernel (float4 units):
//   sA  [0,1024)   sP [1024,2048)   sW1 [2048,3072)   sW2 [3072,4096)
//   sb1/sb2: 128 floats after that.
#define UPD_SMEM_BYTES (4096 * 16 + 128 * 4)     // 66048

// Scratch (allocation-free): ego and side message accumulator (padded rows).
__device__ float g_ego[N_PAD * DIM];
__device__ float g_side[N_PAD * DIM];

// ---------------------------------------------------------------------------
// dummy: occupies launch slot 0 so ncu's "-s 5" lands on the second update.
// ---------------------------------------------------------------------------
__global__ void dummy_kernel() {
    if (blockIdx.x == 0x40000000) g_side[0] = 0.f;   // never true
}

// ---------------------------------------------------------------------------
// init: g_ego <- ego (0 for pad rows), g_side <- 0, out cols [0,64) <- ego.
// One thread per float4. Grid: N_PAD*16/256 = 9376 blocks.
// ---------------------------------------------------------------------------
__global__ void init_kernel(const float* __restrict__ ego_in,
                            float* __restrict__ out) {
    int t = blockIdx.x * 256 + threadIdx.x;          // float4 index < N_PAD*16
    bool real = (t < N_NODES * 16);
    float4 v = real ? ((const float4*)ego_in)[t]
                    : make_float4(0.f, 0.f, 0.f, 0.f);
    ((float4*)g_ego)[t]  = v;
    ((float4*)g_side)[t] = make_float4(0.f, 0.f, 0.f, 0.f);
    if (real) {
        int i = t >> 4;        // node
        int c = t & 15;        // float4 chunk within row
        ((float4*)out)[i * 64 + c] = v;              // out row = 64 float4
    }
}

// ---------------------------------------------------------------------------
// spmm: side[row] += val * ego[col]. 4 edges/thread, float4 chunk/thread,
// vectorized index loads + 4-deep gather MLP + red.global.add.v4.f32.
// ---------------------------------------------------------------------------
__global__ void __launch_bounds__(256) spmm_kernel(
        const int*   __restrict__ rows,
        const int*   __restrict__ cols,
        const float* __restrict__ vals) {
    int t = blockIdx.x * 256 + threadIdx.x;
    int g = t >> 4;        // edge group of 4
    int c = t & 15;        // float4 chunk within the 64-float row
    int4   r4 = __ldg((const int4*)  rows + g);
    int4   c4 = __ldg((const int4*)  cols + g);
    float4 v4 = __ldg((const float4*)vals + g);
    const float4* egop = (const float4*)g_ego;
    float4 x0 = __ldg(egop + (c4.x * 16 + c));
    float4 x1 = __ldg(egop + (c4.y * 16 + c));
    float4 x2 = __ldg(egop + (c4.z * 16 + c));
    float4 x3 = __ldg(egop + (c4.w * 16 + c));

    float* d0 = g_side + r4.x * DIM + c * 4;
    float* d1 = g_side + r4.y * DIM + c * 4;
    float* d2 = g_side + r4.z * DIM + c * 4;
    float* d3 = g_side + r4.w * DIM + c * 4;
    asm volatile("red.global.add.v4.f32 [%0], {%1,%2,%3,%4};"
                 :: "l"(d0), "f"(v4.x*x0.x), "f"(v4.x*x0.y), "f"(v4.x*x0.z), "f"(v4.x*x0.w) : "memory");
    asm volatile("red.global.add.v4.f32 [%0], {%1,%2,%3,%4};"
                 :: "l"(d1), "f"(v4.y*x1.x), "f"(v4.y*x1.y), "f"(v4.y*x1.z), "f"(v4.y*x1.w) : "memory");
    asm volatile("red.global.add.v4.f32 [%0], {%1,%2,%3,%4};"
                 :: "l"(d2), "f"(v4.z*x2.x), "f"(v4.z*x2.y), "f"(v4.z*x2.z), "f"(v4.z*x2.w) : "memory");
    asm volatile("red.global.add.v4.f32 [%0], {%1,%2,%3,%4};"
                 :: "l"(d3), "f"(v4.w*x3.x), "f"(v4.w*x3.y), "f"(v4.w*x3.z), "f"(v4.w*x3.w) : "memory");
}

// ---------------------------------------------------------------------------
// update: register-tiled dual GEMM (dynamic smem, 66048 B, opt-in attr).
// Block = 64 nodes x 64 dims, 256 threads, thread tile 4 nodes x 4 dims for
// BOTH GEMMs (32 accumulators). A/P/W1/W2 staged k-major in shared with an
// XOR-(k>>2) float4-chunk swizzle (conflict-light transpose stores AND frag
// loads). Inner loop: 4 LDS.128 + 32 FMA per k.
// Epilogue: lrelu, v = sum, 16-lane shfl row-norm, float4 stores.
// last=1 skips g_ego writeback + side zeroing (init redoes both per replay).
// ---------------------------------------------------------------------------
__global__ void __launch_bounds__(256) update_kernel(
        const float* __restrict__ W1, const float* __restrict__ b1,
        const float* __restrict__ W2, const float* __restrict__ b2,
        float* __restrict__ out, int col4, int last) {
    extern __shared__ float4 smem[];
    float4* sA  = smem;                 // [k][chunk] swizzled, chunk = node>>2
    float4* sP  = smem + 1024;
    float4* sW1 = smem + 2048;          // [k][chunk] swizzled, chunk = j>>2
    float4* sW2 = smem + 3072;
    float*  sb1 = (float*)(smem + 4096);
    float*  sb2 = sb1 + 64;

    int tid = threadIdx.x;
    int tx  = tid & 15;               // dim group  (j = tx*4 + d)
    int ty  = tid >> 4;               // node group (i = ty*4 + n)

    // ---- stage W1/W2 transposed: read W[j][k] float4, scatter to sW[k][j].
    for (int idx = tid; idx < 1024; idx += 256) {
        int j  = idx >> 4;            // 0..63
        int c4 = idx & 15;            // k-chunk: k = 4*c4 + q
        float4 w1 = __ldg((const float4*)W1 + idx);
        float4 w2 = __ldg((const float4*)W2 + idx);
        float a1[4] = {w1.x, w1.y, w1.z, w1.w};
        float a2[4] = {w2.x, w2.y, w2.z, w2.w};
        int phys = ((j >> 2) ^ c4) & 15;          // swizzled chunk
        #pragma unroll
        for (int q = 0; q < 4; q++) {
            int k = 4 * c4 + q;
            ((float*)sW1)[k * 64 + phys * 4 + (j & 3)] = a1[q];
            ((float*)sW2)[k * 64 + phys * 4 + (j & 3)] = a2[q];
        }
    }
    if (tid < 64) { sb1[tid] = b1[tid]; sb2[tid] = b2[tid]; }

    // ---- stage A = ego+side, P = ego*side, transposed; zero side behind us.
    int gbase4 = blockIdx.x * 1024;               // float4 base of 64 rows
    for (int idx = tid; idx < 1024; idx += 256) {
        int node = idx >> 4;
        int c4   = idx & 15;
        float4 e = ((const float4*)g_ego )[gbase4 + idx];
        float4 s = ((const float4*)g_side)[gbase4 + idx];
        float av[4] = {e.x + s.x, e.y + s.y, e.z + s.z, e.w + s.w};
        float pv[4] = {e.x * s.x, e.y * s.y, e.z * s.z, e.w * s.w};
        int phys = ((node >> 2) ^ c4) & 15;
        #pragma unroll
        for (int q = 0; q < 4; q++) {
            int k = 4 * c4 + q;
            ((float*)sA)[k * 64 + phys * 4 + (node & 3)] = av[q];
            ((float*)sP)[k * 64 + phys * 4 + (node & 3)] = pv[q];
        }
        if (!last) ((float4*)g_side)[gbase4 + idx] = make_float4(0.f, 0.f, 0.f, 0.f);
    }
    __syncthreads();

    // ---- dual GEMM mainloop: 4 LDS.128 + 32 FMA per k.
    float acc1[16], acc2[16];                      // [n*4+d]
    #pragma unroll
    for (int i = 0; i < 16; i++) { acc1[i] = 0.f; acc2[i] = 0.f; }

    #pragma unroll 8
    for (int k = 0; k < 64; k++) {
        int sw = (k >> 2) & 15;
        float4 a  = sA [k * 16 + (ty ^ sw)];
        float4 p  = sP [k * 16 + (ty ^ sw)];
        float4 w1 = sW1[k * 16 + (tx ^ sw)];
        float4 w2 = sW2[k * 16 + (tx ^ sw)];
        float av[4] = {a.x, a.y, a.z, a.w};
        float pv[4] = {p.x, p.y, p.z, p.w};
        float u1[4] = {w1.x, w1.y, w1.z, w1.w};
        float u2[4] = {w2.x, w2.y, w2.z, w2.w};
        #pragma unroll
        for (int n = 0; n < 4; n++)
            #pragma unroll
            for (int d = 0; d < 4; d++) {
                acc1[n * 4 + d] = fmaf(av[n], u1[d], acc1[n * 4 + d]);
                acc2[n * 4 + d] = fmaf(pv[n], u2[d], acc2[n * 4 + d]);
            }
    }

    // ---- epilogue: bias + lrelu + sum, row norm over 16 tx-lanes, store.
    float bb1[4] = {sb1[tx*4+0], sb1[tx*4+1], sb1[tx*4+2], sb1[tx*4+3]};
    float bb2[4] = {sb2[tx*4+0], sb2[tx*4+1], sb2[tx*4+2], sb2[tx*4+3]};
    int i0 = blockIdx.x * 64 + ty * 4;

    #pragma unroll
    for (int n = 0; n < 4; n++) {
        float v[4];
        #pragma unroll
        for (int d = 0; d < 4; d++) {
            float y1 = acc1[n * 4 + d] + bb1[d];
            float y2 = acc2[n * 4 + d] + bb2[d];
            y1 = (y1 >= 0.f) ? y1 : NEG_SLOPE * y1;
            y2 = (y2 >= 0.f) ? y2 : NEG_SLOPE * y2;
            v[d] = y1 + y2;
        }
        float ss = v[0]*v[0] + v[1]*v[1] + v[2]*v[2] + v[3]*v[3];
        ss += __shfl_xor_sync(0xffffffffu, ss, 1);
        ss += __shfl_xor_sync(0xffffffffu, ss, 2);
        ss += __shfl_xor_sync(0xffffffffu, ss, 4);
        ss += __shfl_xor_sync(0xffffffffu, ss, 8);
        float inv = 1.0f / fmaxf(sqrtf(ss), 1e-12f);
        int i = i0 + n;
        float4 vv = make_float4(v[0], v[1], v[2], v[3]);
        if (!last) ((float4*)g_ego)[i * 16 + tx] = vv;       // next-layer ego
        if (i < N_NODES)
            ((float4*)out)[i * 64 + col4 + tx] =
                make_float4(v[0]*inv, v[1]*inv, v[2]*inv, v[3]*inv);
    }
}

// ---------------------------------------------------------------------------
// Inputs: edge_rows(i32), edge_cols(i32), edge_vals(f32), ego(f32 N*64),
// W1(3*64*64), b1(3*64), W2(3*64*64), b2(3*64).
// Output: float32 [150000, 256] rows = [ego | norm1 | norm2 | norm3].
// ---------------------------------------------------------------------------
extern "C" void kernel_launch(void* const* d_in, const int* in_sizes, int n_in,
                              void* d_out, int out_size) {
    const int*   rows = (const int*)  d_in[0];
    const int*   cols = (const int*)  d_in[1];
    const float* vals = (const float*)d_in[2];
    const float* ego  = (const float*)d_in[3];
    const float* W1   = (const float*)d_in[4];
    const float* b1   = (const float*)d_in[5];
    const float* W2   = (const float*)d_in[6];
    const float* b2   = (const float*)d_in[7];
    float* out = (float*)d_out;

    // Opt in to >48KB dynamic smem (idempotent; host-side immediate call,
    // not a stream op -> graph-capture safe).
    cudaFuncSetAttribute(update_kernel,
                         cudaFuncAttributeMaxDynamicSharedMemorySize,
                         UPD_SMEM_BYTES);

    dummy_kernel<<<1, 32>>>();                                    // launch 0
    init_kernel<<<(N_PAD * 16) / 256, 256>>>(ego, out);           // launch 1
    for (int k = 0; k < 3; k++) {
        spmm_kernel<<<(N_EDGES / 4 * 16) / 256, 256>>>(rows, cols, vals);
        update_kernel<<<UPD_BLOCKS, 256, UPD_SMEM_BYTES>>>(
            W1 + k * 4096, b1 + k * 64,
            W2 + k * 4096, b2 + k * 64,
            out, (k + 1) * 16, k == 2);
    }
}